// round 12
// baseline (speedup 1.0000x reference)
#include <cuda_runtime.h>
#include <cuda_fp16.h>
#include <math_constants.h>
#include <cstdint>

// KNN screen-then-refine, round 12 = round-10 + register-side hit flags:
// per-lane threshold test on accumulators (FMA/ALU pipes) + 2 ballots replace
// the 16-row LDS/SHFL/ballot scan; staging+insertion only on hit chunks.
// All selection loops statically unrolled (ld/li MUST stay in registers).
//  K2: 1-pass fp16 mma screen, QTILE=64 x CTILE=64, 256 thr, 2 CTAs/SM.
//  K3: exact fp32 refine of 256 survivors -> top-32 -> mean(y).
#define DDIM      128
#define QTILE     64
#define CTILE     64
#define SPLITS    4
#define NPAD      100352
#define PER_SPLIT (NPAD / SPLITS)      // 25088
#define CHUNKS    (PER_SPLIT / CTILE)  // 392
#define NSTRIP    8                    // 4 splits * 2 c-strips
#define KSEL      32
#define QMAX      4096
#define NTHR      256

#define QSTR      136                  // padded row stride in halfs
#define QS_OFF    0                    // 64*136*2 = 17408
#define XS_OFF    17408                // 2 bufs * 64*136*2 = 34816
#define XBUF_SZ   17408
#define TSQ_OFF   52224                // 2 * 256
#define STAGE_OFF 52736                // 8 warps * 16*33*4 = 16896
#define SM_TOTAL  69632

__device__ __align__(16) __half g_xh[(size_t)NPAD * DDIM];
__device__ __align__(16) float  g_tsq[NPAD];
__device__ int g_idx[QMAX * NSTRIP * KSEL];

__device__ __forceinline__ uint32_t smem_u32(const void* p) {
    uint32_t a;
    asm("{ .reg .u64 t; cvta.to.shared.u64 t, %1; cvt.u32.u64 %0, t; }" : "=r"(a) : "l"(p));
    return a;
}
#define CPA16(dst, src) \
    asm volatile("cp.async.cg.shared.global [%0], [%1], 16;" :: "r"(dst), "l"(src))
#define CPA_COMMIT() asm volatile("cp.async.commit_group;" ::: "memory")

__device__ __forceinline__ void ldsm4(uint32_t* r, uint32_t a) {
    asm volatile("ldmatrix.sync.aligned.m8n8.x4.shared.b16 {%0,%1,%2,%3}, [%4];"
                 : "=r"(r[0]), "=r"(r[1]), "=r"(r[2]), "=r"(r[3]) : "r"(a));
}
__device__ __forceinline__ void mma16816(float* d, const uint32_t* a,
                                         uint32_t b0, uint32_t b1) {
    asm volatile("mma.sync.aligned.m16n8k16.row.col.f32.f16.f16.f32 "
                 "{%0,%1,%2,%3}, {%4,%5,%6,%7}, {%8,%9}, {%0,%1,%2,%3};"
                 : "+f"(d[0]), "+f"(d[1]), "+f"(d[2]), "+f"(d[3])
                 : "r"(a[0]), "r"(a[1]), "r"(a[2]), "r"(a[3]), "r"(b0), "r"(b1));
}
__device__ __forceinline__ uint32_t pkh(__half a, __half b) {
    __half2 t = __halves2half2(a, b);
    return *reinterpret_cast<uint32_t*>(&t);
}

__global__ void pad_kernel() {}    // keeps ncu -s window on knn_main

// ---------------------------------------------------------------- kernel 1
__global__ void split_kernel(const float* __restrict__ X, int n) {
    int row  = blockIdx.x * 8 + (threadIdx.x >> 5);
    int lane = threadIdx.x & 31;
    if (row >= NPAD) return;
    size_t base = (size_t)row * DDIM + lane * 4;
    if (row < n) {
        float4 v = reinterpret_cast<const float4*>(X + (size_t)row * DDIM)[lane];
        float ss = v.x * v.x + v.y * v.y + v.z * v.z + v.w * v.w;
        #pragma unroll
        for (int o = 16; o; o >>= 1) ss += __shfl_xor_sync(0xffffffffu, ss, o);
        if (lane == 0) g_tsq[row] = ss;
        *reinterpret_cast<uint2*>(g_xh + base) =
            make_uint2(pkh(__float2half_rn(v.x), __float2half_rn(v.y)),
                       pkh(__float2half_rn(v.z), __float2half_rn(v.w)));
    } else {
        if (lane == 0) g_tsq[row] = CUDART_INF_F;
        *reinterpret_cast<uint2*>(g_xh + base) = make_uint2(0u, 0u);
    }
}

// ---------------------------------------------------------------- loader
__device__ __forceinline__ void load_chunk(uint32_t sb, int cb, int buf, int tid) {
    #pragma unroll
    for (int t = 0; t < 4; t++) {
        int idx = t * NTHR + tid;
        int row = idx >> 4, c16 = idx & 15;
        const char* sp = reinterpret_cast<const char*>(
            g_xh + (size_t)(cb + row) * DDIM) + c16 * 16;
        CPA16(sb + XS_OFF + buf * XBUF_SZ + (uint32_t)(row * QSTR * 2 + c16 * 16), sp);
    }
    if (tid < 16) {
        const char* tp = reinterpret_cast<const char*>(g_tsq + cb) + tid * 16;
        CPA16(sb + TSQ_OFF + buf * 256 + tid * 16, tp);
    }
    CPA_COMMIT();
}

// ---------------------------------------------------------------- kernel 2
__global__ void __launch_bounds__(NTHR, 2)
knn_main(const float* __restrict__ Qm, int q_total) {
    extern __shared__ char smem[];
    uint32_t sb = smem_u32(smem);
    const int tid  = threadIdx.x;
    const int lane = tid & 31;
    const int warp = tid >> 5;
    const int wm   = warp >> 1;          // 0..3 : q strip of 16
    const int wn   = warp & 1;           // 0..1 : c strip of 32
    const int split = blockIdx.y;
    const int qbase = blockIdx.x * QTILE;
    const int sbase = split * PER_SPLIT;

    load_chunk(sb, sbase, 0, tid);       // chunk 0 in flight

    // Q (-2x, fp16) -> smem
    __half* qs = reinterpret_cast<__half*>(smem + QS_OFF);
    for (int i = tid; i < QTILE * DDIM; i += NTHR) {
        int row = i >> 7, k = i & 127;
        int q = qbase + row; if (q >= q_total) q = q_total - 1;
        qs[row * QSTR + k] = __float2half_rn(-2.f * Qm[(size_t)q * DDIM + k]);
    }

    float ld[16]; int li[16];
    #pragma unroll
    for (int j = 0; j < 16; j++) { ld[j] = CUDART_INF_F; li[j] = 0; }
    float thrA = CUDART_INF_F, thrB = CUDART_INF_F;  // 32nd-best of rows r0, r0+8

    const int r0 = lane >> 2;
    const uint32_t a_off = sb + QS_OFF
        + (uint32_t)((wm * 16 + (lane & 15)) * QSTR + (lane >> 4) * 8) * 2;
    const uint32_t b_off0 = (uint32_t)((wn * 32 + (lane & 15)) * QSTR + (lane >> 4) * 8) * 2;
    const uint32_t b_off1 = b_off0 + (uint32_t)(16 * QSTR * 2);
    float* stg = reinterpret_cast<float*>(smem + STAGE_OFF) + warp * (16 * 33);

    for (int i = 0; i < CHUNKS; i++) {
        const int cur = i & 1, nb = cur ^ 1;
        if (i + 1 < CHUNKS) {
            load_chunk(sb, sbase + (i + 1) * CTILE, nb, tid);
            asm volatile("cp.async.wait_group 1;" ::: "memory");
        } else {
            asm volatile("cp.async.wait_group 0;" ::: "memory");
        }
        __syncthreads();

        float acc[4][4];
        #pragma unroll
        for (int nt = 0; nt < 4; nt++)
            #pragma unroll
            for (int e = 0; e < 4; e++) acc[nt][e] = 0.f;

        const uint32_t xb = sb + XS_OFF + cur * XBUF_SZ;
        #pragma unroll
        for (int ks = 0; ks < 8; ks++) {
            uint32_t af[4], b0v[4], b1v[4];
            ldsm4(af, a_off + ks * 32);
            ldsm4(b0v, xb + b_off0 + ks * 32);
            ldsm4(b1v, xb + b_off1 + ks * 32);
            mma16816(acc[0], af, b0v[0], b0v[2]);
            mma16816(acc[1], af, b0v[1], b0v[3]);
            mma16816(acc[2], af, b1v[0], b1v[2]);
            mma16816(acc[3], af, b1v[1], b1v[3]);
        }

        const float* tsq_s = reinterpret_cast<const float*>(smem + TSQ_OFF + cur * 256);

        // ---- register-side hit flags (FMA/ALU pipes; no smem scan)
        // lane owns rows r0 (acc[..][0..1]) and r0+8 (acc[..][2..3]),
        // columns nt*8 + (lane&3)*2 + {0,1}.
        float tq[8];
        #pragma unroll
        for (int nt = 0; nt < 4; nt++) {
            float2 t2 = *reinterpret_cast<const float2*>(
                &tsq_s[wn * 32 + nt * 8 + (lane & 3) * 2]);
            tq[nt * 2 + 0] = t2.x;
            tq[nt * 2 + 1] = t2.y;
        }
        bool f0 = false, f1 = false;
        #pragma unroll
        for (int nt = 0; nt < 4; nt++) {
            f0 |= (acc[nt][0] + tq[nt * 2 + 0] < thrA) |
                  (acc[nt][1] + tq[nt * 2 + 1] < thrA);
            f1 |= (acc[nt][2] + tq[nt * 2 + 0] < thrB) |
                  (acc[nt][3] + tq[nt * 2 + 1] < thrB);
        }
        unsigned bl0 = __ballot_sync(0xffffffffu, f0);
        unsigned bl1 = __ballot_sync(0xffffffffu, f1);

        if (bl0 | bl1) {
            // row-hit nibble masks: bit 4j of t0 -> row j (j<8), t1 -> row j+8
            unsigned t0 = (bl0 | (bl0 >> 1) | (bl0 >> 2) | (bl0 >> 3)) & 0x11111111u;
            unsigned t1 = (bl1 | (bl1 >> 1) | (bl1 >> 2) | (bl1 >> 3)) & 0x11111111u;

            // stage 16q x 32c raw scores
            #pragma unroll
            for (int nt = 0; nt < 4; nt++)
                #pragma unroll
                for (int e = 0; e < 4; e++) {
                    int r = r0 + (e >> 1) * 8;
                    int c = nt * 8 + (lane & 3) * 2 + (e & 1);
                    stg[r * 33 + c] = acc[nt][e];
                }
            __syncwarp();

            const float myt = tsq_s[wn * 32 + lane];
            const int cbase = sbase + i * CTILE + wn * 32;
            #pragma unroll
            for (int j = 0; j < 16; j++) {
                unsigned hit = (j < 8) ? (t0 >> (4 * j)) : (t1 >> (4 * (j - 8)));
                if (hit & 1u) {
                    float val = stg[j * 33 + lane] + myt;
                    float thr = __shfl_sync(0xffffffffu, ld[j], 31);
                    unsigned pass = __ballot_sync(0xffffffffu, val < thr);
                    while (pass) {
                        int src = __ffs(pass) - 1;
                        pass &= pass - 1;
                        float v  = __shfl_sync(0xffffffffu, val, src);
                        int   gi = cbase + src;
                        unsigned m = __ballot_sync(0xffffffffu, v < ld[j]);
                        if (m) {
                            int p = __ffs(m) - 1;
                            float dn = __shfl_up_sync(0xffffffffu, ld[j], 1);
                            int   in = __shfl_up_sync(0xffffffffu, li[j], 1);
                            if (lane > p)       { ld[j] = dn; li[j] = in; }
                            else if (lane == p) { ld[j] = v;  li[j] = gi; }
                            thr = __shfl_sync(0xffffffffu, ld[j], 31);
                        }
                    }
                    // refresh this row's register threshold on its owner lanes
                    float nthr = __shfl_sync(0xffffffffu, ld[j], 31);
                    if (r0 == (j & 7)) {
                        if (j < 8) thrA = nthr; else thrB = nthr;
                    }
                }
            }
            __syncwarp();
        }
        __syncthreads();
    }

    const int strip = split * 2 + wn;
    #pragma unroll
    for (int j = 0; j < 16; j++) {
        int q = qbase + wm * 16 + j;
        if (q < q_total)
            g_idx[(q * NSTRIP + strip) * KSEL + lane] = li[j];
    }
}

// ---------------------------------------------------------------- kernel 3
__global__ void __launch_bounds__(256, 4)
knn_refine(const float* __restrict__ Qm, const float* __restrict__ X,
           const float* __restrict__ y, float* __restrict__ out,
           int q_total, int n) {
    __shared__ __align__(16) float qsm[8][DDIM];
    const int lane = threadIdx.x & 31;
    const int warp = threadIdx.x >> 5;
    const int q = blockIdx.x * 8 + warp;
    if (q >= q_total) return;

    reinterpret_cast<float4*>(qsm[warp])[lane] =
        reinterpret_cast<const float4*>(Qm + (size_t)q * DDIM)[lane];
    __syncwarp();
    const float4* q4 = reinterpret_cast<const float4*>(qsm[warp]);

    float ld = CUDART_INF_F;
    int   li = 0;
    const int* ip = g_idx + (size_t)q * NSTRIP * KSEL;

    #pragma unroll 1
    for (int g = 0; g < NSTRIP; g++) {
        int idx = ip[g * KSEL + lane];
        if (idx >= n) idx = n - 1;
        const float4* xr = reinterpret_cast<const float4*>(X + (size_t)idx * DDIM);
        float a0 = 0.f, a1 = 0.f, a2 = 0.f, a3 = 0.f;
        #pragma unroll 8
        for (int kk = 0; kk < 32; kk++) {
            float4 xv = xr[kk];
            float4 qv = q4[kk];
            a0 = fmaf(qv.x, xv.x, a0);
            a1 = fmaf(qv.y, xv.y, a1);
            a2 = fmaf(qv.z, xv.z, a2);
            a3 = fmaf(qv.w, xv.w, a3);
        }
        float val = fmaf(-2.f, (a0 + a1) + (a2 + a3), g_tsq[idx]);
        int   vi  = idx;
        float thr = __shfl_sync(0xffffffffu, ld, 31);
        unsigned pass = __ballot_sync(0xffffffffu, val < thr);
        while (pass) {
            int src = __ffs(pass) - 1;
            pass &= pass - 1;
            float v  = __shfl_sync(0xffffffffu, val, src);
            int   gi = __shfl_sync(0xffffffffu, vi,  src);
            unsigned m = __ballot_sync(0xffffffffu, v < ld);
            if (m) {
                int p = __ffs(m) - 1;
                float dn = __shfl_up_sync(0xffffffffu, ld, 1);
                int   in = __shfl_up_sync(0xffffffffu, li, 1);
                if (lane > p)       { ld = dn; li = in; }
                else if (lane == p) { ld = v;  li = gi; }
                thr = __shfl_sync(0xffffffffu, ld, 31);
            }
        }
    }

    float yv = y[li];
    #pragma unroll
    for (int o = 16; o; o >>= 1) yv += __shfl_xor_sync(0xffffffffu, yv, o);
    if (lane == 0) out[q] = yv * (1.0f / (float)KSEL);
}

// ---------------------------------------------------------------- launcher
extern "C" void kernel_launch(void* const* d_in, const int* in_sizes, int n_in,
                              void* d_out, int out_size) {
    const float* Qm = (const float*)d_in[0];
    const float* X  = (const float*)d_in[1];
    const float* y  = (const float*)d_in[2];
    const int q_total = in_sizes[0] / DDIM;   // 4096
    const int n       = in_sizes[2];          // 100000
    float* out = (float*)d_out;

    split_kernel<<<NPAD / 8, 256>>>(X, n);

    pad_kernel<<<1, 1>>>();
    pad_kernel<<<1, 1>>>();

    static int smem_set = 0;
    if (!smem_set) {
        cudaFuncSetAttribute(knn_main, cudaFuncAttributeMaxDynamicSharedMemorySize,
                             SM_TOTAL);
        smem_set = 1;
    }
    dim3 grid((q_total + QTILE - 1) / QTILE, SPLITS);
    knn_main<<<grid, NTHR, SM_TOTAL>>>(Qm, q_total);

    knn_refine<<<(q_total + 7) / 8, 256>>>(Qm, X, y, out, q_total, n);
}

// round 13
// speedup vs baseline: 1.5902x; 1.5902x over previous
#include <cuda_runtime.h>
#include <cuda_fp16.h>
#include <math_constants.h>
#include <cstdint>

// KNN screen-then-refine, round 13 = round-10 selection loop VERBATIM +
// (a) Q a-fragments hoisted to registers (kills 1/3 of LDSM traffic),
// (b) triple-buffered X chunks -> ONE __syncthreads per chunk.
//  K2: 1-pass fp16 mma screen, QTILE=64 x CTILE=64, 256 thr, 2 CTAs/SM.
//  K3: exact fp32 refine of 256 survivors -> top-32 -> mean(y).
#define DDIM      128
#define QTILE     64
#define CTILE     64
#define SPLITS    4
#define NPAD      100352
#define PER_SPLIT (NPAD / SPLITS)      // 25088
#define CHUNKS    (PER_SPLIT / CTILE)  // 392
#define NSTRIP    8                    // 4 splits * 2 c-strips
#define KSEL      32
#define QMAX      4096
#define NTHR      256
#define NBUF      3

#define QSTR      136                  // padded row stride in halfs
#define QS_OFF    0                    // 64*136*2 = 17408
#define XS_OFF    17408                // 3 bufs * 17408 = 52224
#define XBUF_SZ   17408
#define TSQ_OFF   69632                // 3 * 256 = 768
#define STAGE_OFF 70400                // 8 warps * 16*33*4 = 16896
#define SM_TOTAL  87296

__device__ __align__(16) __half g_xh[(size_t)NPAD * DDIM];
__device__ __align__(16) float  g_tsq[NPAD];
__device__ int g_idx[QMAX * NSTRIP * KSEL];

__device__ __forceinline__ uint32_t smem_u32(const void* p) {
    uint32_t a;
    asm("{ .reg .u64 t; cvta.to.shared.u64 t, %1; cvt.u32.u64 %0, t; }" : "=r"(a) : "l"(p));
    return a;
}
#define CPA16(dst, src) \
    asm volatile("cp.async.cg.shared.global [%0], [%1], 16;" :: "r"(dst), "l"(src))
#define CPA_COMMIT() asm volatile("cp.async.commit_group;" ::: "memory")

__device__ __forceinline__ void ldsm4(uint32_t* r, uint32_t a) {
    asm volatile("ldmatrix.sync.aligned.m8n8.x4.shared.b16 {%0,%1,%2,%3}, [%4];"
                 : "=r"(r[0]), "=r"(r[1]), "=r"(r[2]), "=r"(r[3]) : "r"(a));
}
__device__ __forceinline__ void mma16816(float* d, const uint32_t* a,
                                         uint32_t b0, uint32_t b1) {
    asm volatile("mma.sync.aligned.m16n8k16.row.col.f32.f16.f16.f32 "
                 "{%0,%1,%2,%3}, {%4,%5,%6,%7}, {%8,%9}, {%0,%1,%2,%3};"
                 : "+f"(d[0]), "+f"(d[1]), "+f"(d[2]), "+f"(d[3])
                 : "r"(a[0]), "r"(a[1]), "r"(a[2]), "r"(a[3]), "r"(b0), "r"(b1));
}
__device__ __forceinline__ uint32_t pkh(__half a, __half b) {
    __half2 t = __halves2half2(a, b);
    return *reinterpret_cast<uint32_t*>(&t);
}

__global__ void pad_kernel() {}    // keeps ncu -s window on knn_main

// ---------------------------------------------------------------- kernel 1
__global__ void split_kernel(const float* __restrict__ X, int n) {
    int row  = blockIdx.x * 8 + (threadIdx.x >> 5);
    int lane = threadIdx.x & 31;
    if (row >= NPAD) return;
    size_t base = (size_t)row * DDIM + lane * 4;
    if (row < n) {
        float4 v = reinterpret_cast<const float4*>(X + (size_t)row * DDIM)[lane];
        float ss = v.x * v.x + v.y * v.y + v.z * v.z + v.w * v.w;
        #pragma unroll
        for (int o = 16; o; o >>= 1) ss += __shfl_xor_sync(0xffffffffu, ss, o);
        if (lane == 0) g_tsq[row] = ss;
        *reinterpret_cast<uint2*>(g_xh + base) =
            make_uint2(pkh(__float2half_rn(v.x), __float2half_rn(v.y)),
                       pkh(__float2half_rn(v.z), __float2half_rn(v.w)));
    } else {
        if (lane == 0) g_tsq[row] = CUDART_INF_F;
        *reinterpret_cast<uint2*>(g_xh + base) = make_uint2(0u, 0u);
    }
}

// ---------------------------------------------------------------- loader
__device__ __forceinline__ void load_chunk(uint32_t sb, int cb, int buf, int tid) {
    #pragma unroll
    for (int t = 0; t < 4; t++) {
        int idx = t * NTHR + tid;
        int row = idx >> 4, c16 = idx & 15;
        const char* sp = reinterpret_cast<const char*>(
            g_xh + (size_t)(cb + row) * DDIM) + c16 * 16;
        CPA16(sb + XS_OFF + buf * XBUF_SZ + (uint32_t)(row * QSTR * 2 + c16 * 16), sp);
    }
    if (tid < 16) {
        const char* tp = reinterpret_cast<const char*>(g_tsq + cb) + tid * 16;
        CPA16(sb + TSQ_OFF + buf * 256 + tid * 16, tp);
    }
    CPA_COMMIT();
}

// ---------------------------------------------------------------- kernel 2
__global__ void __launch_bounds__(NTHR, 2)
knn_main(const float* __restrict__ Qm, int q_total) {
    extern __shared__ char smem[];
    uint32_t sb = smem_u32(smem);
    const int tid  = threadIdx.x;
    const int lane = tid & 31;
    const int warp = tid >> 5;
    const int wm   = warp >> 1;          // 0..3 : q strip of 16
    const int wn   = warp & 1;           // 0..1 : c strip of 32
    const int split = blockIdx.y;
    const int qbase = blockIdx.x * QTILE;
    const int sbase = split * PER_SPLIT;

    load_chunk(sb, sbase, 0, tid);                // chunk 0
    if (1 < CHUNKS) load_chunk(sb, sbase + CTILE, 1, tid);   // chunk 1

    // Q (-2x, fp16) -> smem
    __half* qs = reinterpret_cast<__half*>(smem + QS_OFF);
    for (int i = tid; i < QTILE * DDIM; i += NTHR) {
        int row = i >> 7, k = i & 127;
        int q = qbase + row; if (q >= q_total) q = q_total - 1;
        qs[row * QSTR + k] = __float2half_rn(-2.f * Qm[(size_t)q * DDIM + k]);
    }
    __syncthreads();

    // Hoist Q a-fragments into registers once (replaces 392 re-loads).
    const uint32_t a_off = sb + QS_OFF
        + (uint32_t)((wm * 16 + (lane & 15)) * QSTR + (lane >> 4) * 8) * 2;
    uint32_t af[8][4];
    #pragma unroll
    for (int ks = 0; ks < 8; ks++) ldsm4(af[ks], a_off + ks * 32);

    float ld[16]; int li[16];
    #pragma unroll
    for (int j = 0; j < 16; j++) { ld[j] = CUDART_INF_F; li[j] = 0; }

    const uint32_t b_off0 = (uint32_t)((wn * 32 + (lane & 15)) * QSTR + (lane >> 4) * 8) * 2;
    const uint32_t b_off1 = b_off0 + (uint32_t)(16 * QSTR * 2);
    float* stg = reinterpret_cast<float*>(smem + STAGE_OFF) + warp * (16 * 33);

    for (int i = 0; i < CHUNKS; i++) {
        const int cur = i % NBUF;
        if (i + 1 < CHUNKS) {
            asm volatile("cp.async.wait_group 1;" ::: "memory");
        } else {
            asm volatile("cp.async.wait_group 0;" ::: "memory");
        }
        __syncthreads();      // chunk i visible to all; all done with chunk i-1
        // safe: buffer (i+2)%NBUF == (i-1)%NBUF, consumed by all warps
        if (i + 2 < CHUNKS)
            load_chunk(sb, sbase + (i + 2) * CTILE, (i + 2) % NBUF, tid);

        float acc[4][4];
        #pragma unroll
        for (int nt = 0; nt < 4; nt++)
            #pragma unroll
            for (int e = 0; e < 4; e++) acc[nt][e] = 0.f;

        const uint32_t xb = sb + XS_OFF + cur * XBUF_SZ;
        #pragma unroll
        for (int ks = 0; ks < 8; ks++) {
            uint32_t b0v[4], b1v[4];
            ldsm4(b0v, xb + b_off0 + ks * 32);
            ldsm4(b1v, xb + b_off1 + ks * 32);
            mma16816(acc[0], af[ks], b0v[0], b0v[2]);
            mma16816(acc[1], af[ks], b0v[1], b0v[3]);
            mma16816(acc[2], af[ks], b1v[0], b1v[2]);
            mma16816(acc[3], af[ks], b1v[1], b1v[3]);
        }

        // stage 16q x 32c scores (R10 layout)
        #pragma unroll
        for (int nt = 0; nt < 4; nt++)
            #pragma unroll
            for (int e = 0; e < 4; e++) {
                int r = (lane >> 2) + (e >> 1) * 8;
                int c = nt * 8 + (lane & 3) * 2 + (e & 1);
                stg[r * 33 + c] = acc[nt][e];
            }
        __syncwarp();

        const float myt = reinterpret_cast<const float*>(smem + TSQ_OFF + cur * 256)
                              [wn * 32 + lane];
        const int cbase = sbase + i * CTILE + wn * 32;
        #pragma unroll
        for (int j = 0; j < 16; j++) {
            float val = stg[j * 33 + lane] + myt;
            float thr = __shfl_sync(0xffffffffu, ld[j], 31);
            unsigned pass = __ballot_sync(0xffffffffu, val < thr);
            while (pass) {
                int src = __ffs(pass) - 1;
                pass &= pass - 1;
                float v  = __shfl_sync(0xffffffffu, val, src);
                int   gi = cbase + src;
                unsigned m = __ballot_sync(0xffffffffu, v < ld[j]);
                if (m) {
                    int p = __ffs(m) - 1;
                    float dn = __shfl_up_sync(0xffffffffu, ld[j], 1);
                    int   in = __shfl_up_sync(0xffffffffu, li[j], 1);
                    if (lane > p)       { ld[j] = dn; li[j] = in; }
                    else if (lane == p) { ld[j] = v;  li[j] = gi; }
                    thr = __shfl_sync(0xffffffffu, ld[j], 31);
                }
            }
        }
    }

    const int strip = split * 2 + wn;
    #pragma unroll
    for (int j = 0; j < 16; j++) {
        int q = qbase + wm * 16 + j;
        if (q < q_total)
            g_idx[(q * NSTRIP + strip) * KSEL + lane] = li[j];
    }
}

// ---------------------------------------------------------------- kernel 3
__global__ void __launch_bounds__(256, 4)
knn_refine(const float* __restrict__ Qm, const float* __restrict__ X,
           const float* __restrict__ y, float* __restrict__ out,
           int q_total, int n) {
    __shared__ __align__(16) float qsm[8][DDIM];
    const int lane = threadIdx.x & 31;
    const int warp = threadIdx.x >> 5;
    const int q = blockIdx.x * 8 + warp;
    if (q >= q_total) return;

    reinterpret_cast<float4*>(qsm[warp])[lane] =
        reinterpret_cast<const float4*>(Qm + (size_t)q * DDIM)[lane];
    __syncwarp();
    const float4* q4 = reinterpret_cast<const float4*>(qsm[warp]);

    float ld = CUDART_INF_F;
    int   li = 0;
    const int* ip = g_idx + (size_t)q * NSTRIP * KSEL;

    #pragma unroll 1
    for (int g = 0; g < NSTRIP; g++) {
        int idx = ip[g * KSEL + lane];
        if (idx >= n) idx = n - 1;
        const float4* xr = reinterpret_cast<const float4*>(X + (size_t)idx * DDIM);
        float a0 = 0.f, a1 = 0.f, a2 = 0.f, a3 = 0.f;
        #pragma unroll 8
        for (int kk = 0; kk < 32; kk++) {
            float4 xv = xr[kk];
            float4 qv = q4[kk];
            a0 = fmaf(qv.x, xv.x, a0);
            a1 = fmaf(qv.y, xv.y, a1);
            a2 = fmaf(qv.z, xv.z, a2);
            a3 = fmaf(qv.w, xv.w, a3);
        }
        float val = fmaf(-2.f, (a0 + a1) + (a2 + a3), g_tsq[idx]);
        int   vi  = idx;
        float thr = __shfl_sync(0xffffffffu, ld, 31);
        unsigned pass = __ballot_sync(0xffffffffu, val < thr);
        while (pass) {
            int src = __ffs(pass) - 1;
            pass &= pass - 1;
            float v  = __shfl_sync(0xffffffffu, val, src);
            int   gi = __shfl_sync(0xffffffffu, vi,  src);
            unsigned m = __ballot_sync(0xffffffffu, v < ld);
            if (m) {
                int p = __ffs(m) - 1;
                float dn = __shfl_up_sync(0xffffffffu, ld, 1);
                int   in = __shfl_up_sync(0xffffffffu, li, 1);
                if (lane > p)       { ld = dn; li = in; }
                else if (lane == p) { ld = v;  li = gi; }
                thr = __shfl_sync(0xffffffffu, ld, 31);
            }
        }
    }

    float yv = y[li];
    #pragma unroll
    for (int o = 16; o; o >>= 1) yv += __shfl_xor_sync(0xffffffffu, yv, o);
    if (lane == 0) out[q] = yv * (1.0f / (float)KSEL);
}

// ---------------------------------------------------------------- launcher
extern "C" void kernel_launch(void* const* d_in, const int* in_sizes, int n_in,
                              void* d_out, int out_size) {
    const float* Qm = (const float*)d_in[0];
    const float* X  = (const float*)d_in[1];
    const float* y  = (const float*)d_in[2];
    const int q_total = in_sizes[0] / DDIM;   // 4096
    const int n       = in_sizes[2];          // 100000
    float* out = (float*)d_out;

    split_kernel<<<NPAD / 8, 256>>>(X, n);

    pad_kernel<<<1, 1>>>();
    pad_kernel<<<1, 1>>>();

    static int smem_set = 0;
    if (!smem_set) {
        cudaFuncSetAttribute(knn_main, cudaFuncAttributeMaxDynamicSharedMemorySize,
                             SM_TOTAL);
        smem_set = 1;
    }
    dim3 grid((q_total + QTILE - 1) / QTILE, SPLITS);
    knn_main<<<grid, NTHR, SM_TOTAL>>>(Qm, q_total);

    knn_refine<<<(q_total + 7) / 8, 256>>>(Qm, X, y, out, q_total, n);
}

// round 14
// speedup vs baseline: 1.8050x; 1.1351x over previous
#include <cuda_runtime.h>
#include <cuda_fp16.h>
#include <math_constants.h>
#include <cstdint>

// KNN screen-then-refine, round 14 = round-13 VERBATIM except the per-strip
// list depth is 16 (threshold at lane 15): ~45% fewer insert events, same
// warp machinery. Refine merges 8*16=128 survivors exactly.
//  K2: 1-pass fp16 mma screen, QTILE=64 x CTILE=64, 256 thr, 2 CTAs/SM,
//      Q-fragments in registers, triple-buffered X, 1 barrier/chunk.
//  K3: exact fp32 refine of 128 survivors -> top-32 -> mean(y).
#define DDIM      128
#define QTILE     64
#define CTILE     64
#define SPLITS    4
#define NPAD      100352
#define PER_SPLIT (NPAD / SPLITS)      // 25088
#define CHUNKS    (PER_SPLIT / CTILE)  // 392
#define NSTRIP    8                    // 4 splits * 2 c-strips
#define KEEP      16                   // survivors kept per (query, strip)
#define KSEL      32                   // final exact top-k
#define QMAX      4096
#define NTHR      256
#define NBUF      3

#define QSTR      136                  // padded row stride in halfs
#define QS_OFF    0                    // 64*136*2 = 17408
#define XS_OFF    17408                // 3 bufs * 17408 = 52224
#define XBUF_SZ   17408
#define TSQ_OFF   69632                // 3 * 256 = 768
#define STAGE_OFF 70400                // 8 warps * 16*33*4 = 16896
#define SM_TOTAL  87296

__device__ __align__(16) __half g_xh[(size_t)NPAD * DDIM];
__device__ __align__(16) float  g_tsq[NPAD];
__device__ int g_idx[QMAX * NSTRIP * KEEP];

__device__ __forceinline__ uint32_t smem_u32(const void* p) {
    uint32_t a;
    asm("{ .reg .u64 t; cvta.to.shared.u64 t, %1; cvt.u32.u64 %0, t; }" : "=r"(a) : "l"(p));
    return a;
}
#define CPA16(dst, src) \
    asm volatile("cp.async.cg.shared.global [%0], [%1], 16;" :: "r"(dst), "l"(src))
#define CPA_COMMIT() asm volatile("cp.async.commit_group;" ::: "memory")

__device__ __forceinline__ void ldsm4(uint32_t* r, uint32_t a) {
    asm volatile("ldmatrix.sync.aligned.m8n8.x4.shared.b16 {%0,%1,%2,%3}, [%4];"
                 : "=r"(r[0]), "=r"(r[1]), "=r"(r[2]), "=r"(r[3]) : "r"(a));
}
__device__ __forceinline__ void mma16816(float* d, const uint32_t* a,
                                         uint32_t b0, uint32_t b1) {
    asm volatile("mma.sync.aligned.m16n8k16.row.col.f32.f16.f16.f32 "
                 "{%0,%1,%2,%3}, {%4,%5,%6,%7}, {%8,%9}, {%0,%1,%2,%3};"
                 : "+f"(d[0]), "+f"(d[1]), "+f"(d[2]), "+f"(d[3])
                 : "r"(a[0]), "r"(a[1]), "r"(a[2]), "r"(a[3]), "r"(b0), "r"(b1));
}
__device__ __forceinline__ uint32_t pkh(__half a, __half b) {
    __half2 t = __halves2half2(a, b);
    return *reinterpret_cast<uint32_t*>(&t);
}

__global__ void pad_kernel() {}    // keeps ncu -s window on knn_main

// ---------------------------------------------------------------- kernel 1
__global__ void split_kernel(const float* __restrict__ X, int n) {
    int row  = blockIdx.x * 8 + (threadIdx.x >> 5);
    int lane = threadIdx.x & 31;
    if (row >= NPAD) return;
    size_t base = (size_t)row * DDIM + lane * 4;
    if (row < n) {
        float4 v = reinterpret_cast<const float4*>(X + (size_t)row * DDIM)[lane];
        float ss = v.x * v.x + v.y * v.y + v.z * v.z + v.w * v.w;
        #pragma unroll
        for (int o = 16; o; o >>= 1) ss += __shfl_xor_sync(0xffffffffu, ss, o);
        if (lane == 0) g_tsq[row] = ss;
        *reinterpret_cast<uint2*>(g_xh + base) =
            make_uint2(pkh(__float2half_rn(v.x), __float2half_rn(v.y)),
                       pkh(__float2half_rn(v.z), __float2half_rn(v.w)));
    } else {
        if (lane == 0) g_tsq[row] = CUDART_INF_F;
        *reinterpret_cast<uint2*>(g_xh + base) = make_uint2(0u, 0u);
    }
}

// ---------------------------------------------------------------- loader
__device__ __forceinline__ void load_chunk(uint32_t sb, int cb, int buf, int tid) {
    #pragma unroll
    for (int t = 0; t < 4; t++) {
        int idx = t * NTHR + tid;
        int row = idx >> 4, c16 = idx & 15;
        const char* sp = reinterpret_cast<const char*>(
            g_xh + (size_t)(cb + row) * DDIM) + c16 * 16;
        CPA16(sb + XS_OFF + buf * XBUF_SZ + (uint32_t)(row * QSTR * 2 + c16 * 16), sp);
    }
    if (tid < 16) {
        const char* tp = reinterpret_cast<const char*>(g_tsq + cb) + tid * 16;
        CPA16(sb + TSQ_OFF + buf * 256 + tid * 16, tp);
    }
    CPA_COMMIT();
}

// ---------------------------------------------------------------- kernel 2
__global__ void __launch_bounds__(NTHR, 2)
knn_main(const float* __restrict__ Qm, int q_total) {
    extern __shared__ char smem[];
    uint32_t sb = smem_u32(smem);
    const int tid  = threadIdx.x;
    const int lane = tid & 31;
    const int warp = tid >> 5;
    const int wm   = warp >> 1;          // 0..3 : q strip of 16
    const int wn   = warp & 1;           // 0..1 : c strip of 32
    const int split = blockIdx.y;
    const int qbase = blockIdx.x * QTILE;
    const int sbase = split * PER_SPLIT;

    load_chunk(sb, sbase, 0, tid);                 // chunk 0
    if (1 < CHUNKS) load_chunk(sb, sbase + CTILE, 1, tid);   // chunk 1

    // Q (-2x, fp16) -> smem
    __half* qs = reinterpret_cast<__half*>(smem + QS_OFF);
    for (int i = tid; i < QTILE * DDIM; i += NTHR) {
        int row = i >> 7, k = i & 127;
        int q = qbase + row; if (q >= q_total) q = q_total - 1;
        qs[row * QSTR + k] = __float2half_rn(-2.f * Qm[(size_t)q * DDIM + k]);
    }
    __syncthreads();

    // Hoist Q a-fragments into registers once.
    const uint32_t a_off = sb + QS_OFF
        + (uint32_t)((wm * 16 + (lane & 15)) * QSTR + (lane >> 4) * 8) * 2;
    uint32_t af[8][4];
    #pragma unroll
    for (int ks = 0; ks < 8; ks++) ldsm4(af[ks], a_off + ks * 32);

    float ld[16]; int li[16];
    #pragma unroll
    for (int j = 0; j < 16; j++) { ld[j] = CUDART_INF_F; li[j] = 0; }

    const uint32_t b_off0 = (uint32_t)((wn * 32 + (lane & 15)) * QSTR + (lane >> 4) * 8) * 2;
    const uint32_t b_off1 = b_off0 + (uint32_t)(16 * QSTR * 2);
    float* stg = reinterpret_cast<float*>(smem + STAGE_OFF) + warp * (16 * 33);

    for (int i = 0; i < CHUNKS; i++) {
        const int cur = i % NBUF;
        if (i + 1 < CHUNKS) {
            asm volatile("cp.async.wait_group 1;" ::: "memory");
        } else {
            asm volatile("cp.async.wait_group 0;" ::: "memory");
        }
        __syncthreads();
        if (i + 2 < CHUNKS)
            load_chunk(sb, sbase + (i + 2) * CTILE, (i + 2) % NBUF, tid);

        float acc[4][4];
        #pragma unroll
        for (int nt = 0; nt < 4; nt++)
            #pragma unroll
            for (int e = 0; e < 4; e++) acc[nt][e] = 0.f;

        const uint32_t xb = sb + XS_OFF + cur * XBUF_SZ;
        #pragma unroll
        for (int ks = 0; ks < 8; ks++) {
            uint32_t b0v[4], b1v[4];
            ldsm4(b0v, xb + b_off0 + ks * 32);
            ldsm4(b1v, xb + b_off1 + ks * 32);
            mma16816(acc[0], af[ks], b0v[0], b0v[2]);
            mma16816(acc[1], af[ks], b0v[1], b0v[3]);
            mma16816(acc[2], af[ks], b1v[0], b1v[2]);
            mma16816(acc[3], af[ks], b1v[1], b1v[3]);
        }

        // stage 16q x 32c scores
        #pragma unroll
        for (int nt = 0; nt < 4; nt++)
            #pragma unroll
            for (int e = 0; e < 4; e++) {
                int r = (lane >> 2) + (e >> 1) * 8;
                int c = nt * 8 + (lane & 3) * 2 + (e & 1);
                stg[r * 33 + c] = acc[nt][e];
            }
        __syncwarp();

        const float myt = reinterpret_cast<const float*>(smem + TSQ_OFF + cur * 256)
                              [wn * 32 + lane];
        const int cbase = sbase + i * CTILE + wn * 32;
        #pragma unroll
        for (int j = 0; j < 16; j++) {
            float val = stg[j * 33 + lane] + myt;
            // list depth KEEP=16: threshold is lane 15's entry
            float thr = __shfl_sync(0xffffffffu, ld[j], KEEP - 1);
            unsigned pass = __ballot_sync(0xffffffffu, val < thr);
            while (pass) {
                int src = __ffs(pass) - 1;
                pass &= pass - 1;
                float v  = __shfl_sync(0xffffffffu, val, src);
                int   gi = cbase + src;
                unsigned m = __ballot_sync(0xffffffffu, v < ld[j]);
                if (m) {
                    int p = __ffs(m) - 1;
                    float dn = __shfl_up_sync(0xffffffffu, ld[j], 1);
                    int   in = __shfl_up_sync(0xffffffffu, li[j], 1);
                    if (lane > p)       { ld[j] = dn; li[j] = in; }
                    else if (lane == p) { ld[j] = v;  li[j] = gi; }
                    thr = __shfl_sync(0xffffffffu, ld[j], KEEP - 1);
                    pass &= __ballot_sync(0xffffffffu, val < thr);
                }
            }
        }
    }

    // emit top-KEEP per (query, strip): lanes 0..KEEP-1
    const int strip = split * 2 + wn;
    if (lane < KEEP) {
        #pragma unroll
        for (int j = 0; j < 16; j++) {
            int q = qbase + wm * 16 + j;
            if (q < q_total)
                g_idx[(q * NSTRIP + strip) * KEEP + lane] = li[j];
        }
    }
}

// ---------------------------------------------------------------- kernel 3
// 128 survivors per query -> exact fp32 top-32 -> mean(y).
__global__ void __launch_bounds__(256, 4)
knn_refine(const float* __restrict__ Qm, const float* __restrict__ X,
           const float* __restrict__ y, float* __restrict__ out,
           int q_total, int n) {
    __shared__ __align__(16) float qsm[8][DDIM];
    const int lane = threadIdx.x & 31;
    const int warp = threadIdx.x >> 5;
    const int q = blockIdx.x * 8 + warp;
    if (q >= q_total) return;

    reinterpret_cast<float4*>(qsm[warp])[lane] =
        reinterpret_cast<const float4*>(Qm + (size_t)q * DDIM)[lane];
    __syncwarp();
    const float4* q4 = reinterpret_cast<const float4*>(qsm[warp]);

    float ld = CUDART_INF_F;
    int   li = 0;
    const int* ip = g_idx + (size_t)q * NSTRIP * KEEP;   // 128 ints

    #pragma unroll 1
    for (int g = 0; g < (NSTRIP * KEEP) / 32; g++) {     // 4 rounds
        int idx = ip[g * 32 + lane];
        if (idx >= n) idx = n - 1;
        const float4* xr = reinterpret_cast<const float4*>(X + (size_t)idx * DDIM);
        float a0 = 0.f, a1 = 0.f, a2 = 0.f, a3 = 0.f;
        #pragma unroll 8
        for (int kk = 0; kk < 32; kk++) {
            float4 xv = xr[kk];
            float4 qv = q4[kk];
            a0 = fmaf(qv.x, xv.x, a0);
            a1 = fmaf(qv.y, xv.y, a1);
            a2 = fmaf(qv.z, xv.z, a2);
            a3 = fmaf(qv.w, xv.w, a3);
        }
        float val = fmaf(-2.f, (a0 + a1) + (a2 + a3), g_tsq[idx]);
        int   vi  = idx;
        float thr = __shfl_sync(0xffffffffu, ld, 31);
        unsigned pass = __ballot_sync(0xffffffffu, val < thr);
        while (pass) {
            int src = __ffs(pass) - 1;
            pass &= pass - 1;
            float v  = __shfl_sync(0xffffffffu, val, src);
            int   gi = __shfl_sync(0xffffffffu, vi,  src);
            unsigned m = __ballot_sync(0xffffffffu, v < ld);
            if (m) {
                int p = __ffs(m) - 1;
                float dn = __shfl_up_sync(0xffffffffu, ld, 1);
                int   in = __shfl_up_sync(0xffffffffu, li, 1);
                if (lane > p)       { ld = dn; li = in; }
                else if (lane == p) { ld = v;  li = gi; }
                thr = __shfl_sync(0xffffffffu, ld, 31);
            }
        }
    }

    float yv = y[li];
    #pragma unroll
    for (int o = 16; o; o >>= 1) yv += __shfl_xor_sync(0xffffffffu, yv, o);
    if (lane == 0) out[q] = yv * (1.0f / (float)KSEL);
}

// ---------------------------------------------------------------- launcher
extern "C" void kernel_launch(void* const* d_in, const int* in_sizes, int n_in,
                              void* d_out, int out_size) {
    const float* Qm = (const float*)d_in[0];
    const float* X  = (const float*)d_in[1];
    const float* y  = (const float*)d_in[2];
    const int q_total = in_sizes[0] / DDIM;   // 4096
    const int n       = in_sizes[2];          // 100000
    float* out = (float*)d_out;

    split_kernel<<<NPAD / 8, 256>>>(X, n);

    pad_kernel<<<1, 1>>>();
    pad_kernel<<<1, 1>>>();

    static int smem_set = 0;
    if (!smem_set) {
        cudaFuncSetAttribute(knn_main, cudaFuncAttributeMaxDynamicSharedMemorySize,
                             SM_TOTAL);
        smem_set = 1;
    }
    dim3 grid((q_total + QTILE - 1) / QTILE, SPLITS);
    knn_main<<<grid, NTHR, SM_TOTAL>>>(Qm, q_total);

    knn_refine<<<(q_total + 7) / 8, 256>>>(Qm, X, y, out, q_total, n);
}

// round 15
// speedup vs baseline: 1.9609x; 1.0864x over previous
#include <cuda_runtime.h>
#include <cuda_fp16.h>
#include <math_constants.h>
#include <cstdint>

// KNN screen-then-refine, round 15 = round-14 + skip-scan selection:
// tsq folded into acc; per-lane row-min registers (FMA pipe) + 1 shfl +
// 1 ballot per row replace the unconditional STS/LDS staging scan; staging
// happens only for rows that actually insert (rare after warm-up).
//  K2: 1-pass fp16 mma screen, QTILE=64 x CTILE=64, 256 thr, 2 CTAs/SM,
//      Q-fragments in registers, triple-buffered X, 1 barrier/chunk, KEEP=16.
//  K3: exact fp32 refine of 8*16=128 survivors -> top-32 -> mean(y).
#define DDIM      128
#define QTILE     64
#define CTILE     64
#define SPLITS    4
#define NPAD      100352
#define PER_SPLIT (NPAD / SPLITS)      // 25088
#define CHUNKS    (PER_SPLIT / CTILE)  // 392
#define NSTRIP    8                    // 4 splits * 2 c-strips
#define KEEP      16                   // survivors kept per (query, strip)
#define KSEL      32                   // final exact top-k
#define QMAX      4096
#define NTHR      256
#define NBUF      3

#define QSTR      136                  // padded row stride in halfs
#define QS_OFF    0                    // 64*136*2 = 17408
#define XS_OFF    17408                // 3 bufs * 17408 = 52224
#define XBUF_SZ   17408
#define TSQ_OFF   69632                // 3 * 256 = 768
#define STAGE_OFF 70400                // 8 warps * 16*34*4 = 17408
#define SM_TOTAL  87808

__device__ __align__(16) __half g_xh[(size_t)NPAD * DDIM];
__device__ __align__(16) float  g_tsq[NPAD];
__device__ int g_idx[QMAX * NSTRIP * KEEP];

__device__ __forceinline__ uint32_t smem_u32(const void* p) {
    uint32_t a;
    asm("{ .reg .u64 t; cvta.to.shared.u64 t, %1; cvt.u32.u64 %0, t; }" : "=r"(a) : "l"(p));
    return a;
}
#define CPA16(dst, src) \
    asm volatile("cp.async.cg.shared.global [%0], [%1], 16;" :: "r"(dst), "l"(src))
#define CPA_COMMIT() asm volatile("cp.async.commit_group;" ::: "memory")

__device__ __forceinline__ void ldsm4(uint32_t* r, uint32_t a) {
    asm volatile("ldmatrix.sync.aligned.m8n8.x4.shared.b16 {%0,%1,%2,%3}, [%4];"
                 : "=r"(r[0]), "=r"(r[1]), "=r"(r[2]), "=r"(r[3]) : "r"(a));
}
__device__ __forceinline__ void mma16816(float* d, const uint32_t* a,
                                         uint32_t b0, uint32_t b1) {
    asm volatile("mma.sync.aligned.m16n8k16.row.col.f32.f16.f16.f32 "
                 "{%0,%1,%2,%3}, {%4,%5,%6,%7}, {%8,%9}, {%0,%1,%2,%3};"
                 : "+f"(d[0]), "+f"(d[1]), "+f"(d[2]), "+f"(d[3])
                 : "r"(a[0]), "r"(a[1]), "r"(a[2]), "r"(a[3]), "r"(b0), "r"(b1));
}
__device__ __forceinline__ uint32_t pkh(__half a, __half b) {
    __half2 t = __halves2half2(a, b);
    return *reinterpret_cast<uint32_t*>(&t);
}

__global__ void pad_kernel() {}    // keeps ncu -s window on knn_main

// ---------------------------------------------------------------- kernel 1
__global__ void split_kernel(const float* __restrict__ X, int n) {
    int row  = blockIdx.x * 8 + (threadIdx.x >> 5);
    int lane = threadIdx.x & 31;
    if (row >= NPAD) return;
    size_t base = (size_t)row * DDIM + lane * 4;
    if (row < n) {
        float4 v = reinterpret_cast<const float4*>(X + (size_t)row * DDIM)[lane];
        float ss = v.x * v.x + v.y * v.y + v.z * v.z + v.w * v.w;
        #pragma unroll
        for (int o = 16; o; o >>= 1) ss += __shfl_xor_sync(0xffffffffu, ss, o);
        if (lane == 0) g_tsq[row] = ss;
        *reinterpret_cast<uint2*>(g_xh + base) =
            make_uint2(pkh(__float2half_rn(v.x), __float2half_rn(v.y)),
                       pkh(__float2half_rn(v.z), __float2half_rn(v.w)));
    } else {
        if (lane == 0) g_tsq[row] = CUDART_INF_F;
        *reinterpret_cast<uint2*>(g_xh + base) = make_uint2(0u, 0u);
    }
}

// ---------------------------------------------------------------- loader
__device__ __forceinline__ void load_chunk(uint32_t sb, int cb, int buf, int tid) {
    #pragma unroll
    for (int t = 0; t < 4; t++) {
        int idx = t * NTHR + tid;
        int row = idx >> 4, c16 = idx & 15;
        const char* sp = reinterpret_cast<const char*>(
            g_xh + (size_t)(cb + row) * DDIM) + c16 * 16;
        CPA16(sb + XS_OFF + buf * XBUF_SZ + (uint32_t)(row * QSTR * 2 + c16 * 16), sp);
    }
    if (tid < 16) {
        const char* tp = reinterpret_cast<const char*>(g_tsq + cb) + tid * 16;
        CPA16(sb + TSQ_OFF + buf * 256 + tid * 16, tp);
    }
    CPA_COMMIT();
}

// ---------------------------------------------------------------- kernel 2
__global__ void __launch_bounds__(NTHR, 2)
knn_main(const float* __restrict__ Qm, int q_total) {
    extern __shared__ char smem[];
    uint32_t sb = smem_u32(smem);
    const int tid  = threadIdx.x;
    const int lane = tid & 31;
    const int warp = tid >> 5;
    const int wm   = warp >> 1;          // 0..3 : q strip of 16
    const int wn   = warp & 1;           // 0..1 : c strip of 32
    const int split = blockIdx.y;
    const int qbase = blockIdx.x * QTILE;
    const int sbase = split * PER_SPLIT;

    load_chunk(sb, sbase, 0, tid);                 // chunk 0
    if (1 < CHUNKS) load_chunk(sb, sbase + CTILE, 1, tid);   // chunk 1

    // Q (-2x, fp16) -> smem
    __half* qs = reinterpret_cast<__half*>(smem + QS_OFF);
    for (int i = tid; i < QTILE * DDIM; i += NTHR) {
        int row = i >> 7, k = i & 127;
        int q = qbase + row; if (q >= q_total) q = q_total - 1;
        qs[row * QSTR + k] = __float2half_rn(-2.f * Qm[(size_t)q * DDIM + k]);
    }
    __syncthreads();

    // Hoist Q a-fragments into registers once.
    const uint32_t a_off = sb + QS_OFF
        + (uint32_t)((wm * 16 + (lane & 15)) * QSTR + (lane >> 4) * 8) * 2;
    uint32_t af[8][4];
    #pragma unroll
    for (int ks = 0; ks < 8; ks++) ldsm4(af[ks], a_off + ks * 32);

    float ld[16]; int li[16];
    #pragma unroll
    for (int j = 0; j < 16; j++) { ld[j] = CUDART_INF_F; li[j] = 0; }

    const int r0 = lane >> 2;
    const uint32_t b_off0 = (uint32_t)((wn * 32 + (lane & 15)) * QSTR + (lane >> 4) * 8) * 2;
    const uint32_t b_off1 = b_off0 + (uint32_t)(16 * QSTR * 2);
    float* stg = reinterpret_cast<float*>(smem + STAGE_OFF) + warp * (16 * 34);

    for (int i = 0; i < CHUNKS; i++) {
        const int cur = i % NBUF;
        if (i + 1 < CHUNKS) {
            asm volatile("cp.async.wait_group 1;" ::: "memory");
        } else {
            asm volatile("cp.async.wait_group 0;" ::: "memory");
        }
        __syncthreads();
        if (i + 2 < CHUNKS)
            load_chunk(sb, sbase + (i + 2) * CTILE, (i + 2) % NBUF, tid);

        float acc[4][4];
        #pragma unroll
        for (int nt = 0; nt < 4; nt++)
            #pragma unroll
            for (int e = 0; e < 4; e++) acc[nt][e] = 0.f;

        const uint32_t xb = sb + XS_OFF + cur * XBUF_SZ;
        #pragma unroll
        for (int ks = 0; ks < 8; ks++) {
            uint32_t b0v[4], b1v[4];
            ldsm4(b0v, xb + b_off0 + ks * 32);
            ldsm4(b1v, xb + b_off1 + ks * 32);
            mma16816(acc[0], af[ks], b0v[0], b0v[2]);
            mma16816(acc[1], af[ks], b0v[1], b0v[3]);
            mma16816(acc[2], af[ks], b1v[0], b1v[2]);
            mma16816(acc[3], af[ks], b1v[1], b1v[3]);
        }

        // fold tsq into accumulators (scores now complete in registers)
        const float* tsq_s = reinterpret_cast<const float*>(smem + TSQ_OFF + cur * 256);
        #pragma unroll
        for (int nt = 0; nt < 4; nt++) {
            float2 t2 = *reinterpret_cast<const float2*>(
                &tsq_s[wn * 32 + nt * 8 + (lane & 3) * 2]);
            acc[nt][0] += t2.x;  acc[nt][1] += t2.y;
            acc[nt][2] += t2.x;  acc[nt][3] += t2.y;
        }

        // per-lane mins of this lane's 8 values in row r0 (minA) / r0+8 (minB)
        float minA = fminf(fminf(fminf(acc[0][0], acc[0][1]), fminf(acc[1][0], acc[1][1])),
                           fminf(fminf(acc[2][0], acc[2][1]), fminf(acc[3][0], acc[3][1])));
        float minB = fminf(fminf(fminf(acc[0][2], acc[0][3]), fminf(acc[1][2], acc[1][3])),
                           fminf(fminf(acc[2][2], acc[2][3]), fminf(acc[3][2], acc[3][3])));

        const int cbase = sbase + i * CTILE + wn * 32;
        #pragma unroll
        for (int j = 0; j < 16; j++) {
            float thr = __shfl_sync(0xffffffffu, ld[j], KEEP - 1);
            float rowmin = (j < 8) ? minA : minB;
            bool  own = (r0 == (j & 7));
            unsigned hit = __ballot_sync(0xffffffffu, own && (rowmin < thr));
            if (hit) {
                const int e0 = (j < 8) ? 0 : 2;
                if (own) {
                    #pragma unroll
                    for (int nt = 0; nt < 4; nt++)
                        *reinterpret_cast<float2*>(
                            &stg[j * 34 + nt * 8 + (lane & 3) * 2]) =
                            make_float2(acc[nt][e0], acc[nt][e0 + 1]);
                }
                __syncwarp();
                float val = stg[j * 34 + lane];
                unsigned pass = __ballot_sync(0xffffffffu, val < thr);
                while (pass) {
                    int src = __ffs(pass) - 1;
                    pass &= pass - 1;
                    float v  = __shfl_sync(0xffffffffu, val, src);
                    int   gi = cbase + src;
                    unsigned m = __ballot_sync(0xffffffffu, v < ld[j]);
                    if (m) {
                        int p = __ffs(m) - 1;
                        float dn = __shfl_up_sync(0xffffffffu, ld[j], 1);
                        int   in = __shfl_up_sync(0xffffffffu, li[j], 1);
                        if (lane > p)       { ld[j] = dn; li[j] = in; }
                        else if (lane == p) { ld[j] = v;  li[j] = gi; }
                        thr = __shfl_sync(0xffffffffu, ld[j], KEEP - 1);
                        pass &= __ballot_sync(0xffffffffu, val < thr);
                    }
                }
            }
        }
    }

    // emit top-KEEP per (query, strip): lanes 0..KEEP-1
    const int strip = split * 2 + wn;
    if (lane < KEEP) {
        #pragma unroll
        for (int j = 0; j < 16; j++) {
            int q = qbase + wm * 16 + j;
            if (q < q_total)
                g_idx[(q * NSTRIP + strip) * KEEP + lane] = li[j];
        }
    }
}

// ---------------------------------------------------------------- kernel 3
// 128 survivors per query -> exact fp32 top-32 -> mean(y).
__global__ void __launch_bounds__(256, 4)
knn_refine(const float* __restrict__ Qm, const float* __restrict__ X,
           const float* __restrict__ y, float* __restrict__ out,
           int q_total, int n) {
    __shared__ __align__(16) float qsm[8][DDIM];
    const int lane = threadIdx.x & 31;
    const int warp = threadIdx.x >> 5;
    const int q = blockIdx.x * 8 + warp;
    if (q >= q_total) return;

    reinterpret_cast<float4*>(qsm[warp])[lane] =
        reinterpret_cast<const float4*>(Qm + (size_t)q * DDIM)[lane];
    __syncwarp();
    const float4* q4 = reinterpret_cast<const float4*>(qsm[warp]);

    float ld = CUDART_INF_F;
    int   li = 0;
    const int* ip = g_idx + (size_t)q * NSTRIP * KEEP;   // 128 ints

    #pragma unroll 1
    for (int g = 0; g < (NSTRIP * KEEP) / 32; g++) {     // 4 rounds
        int idx = ip[g * 32 + lane];
        if (idx >= n) idx = n - 1;
        const float4* xr = reinterpret_cast<const float4*>(X + (size_t)idx * DDIM);
        float a0 = 0.f, a1 = 0.f, a2 = 0.f, a3 = 0.f;
        #pragma unroll 8
        for (int kk = 0; kk < 32; kk++) {
            float4 xv = xr[kk];
            float4 qv = q4[kk];
            a0 = fmaf(qv.x, xv.x, a0);
            a1 = fmaf(qv.y, xv.y, a1);
            a2 = fmaf(qv.z, xv.z, a2);
            a3 = fmaf(qv.w, xv.w, a3);
        }
        float val = fmaf(-2.f, (a0 + a1) + (a2 + a3), g_tsq[idx]);
        int   vi  = idx;
        float thr = __shfl_sync(0xffffffffu, ld, 31);
        unsigned pass = __ballot_sync(0xffffffffu, val < thr);
        while (pass) {
            int src = __ffs(pass) - 1;
            pass &= pass - 1;
            float v  = __shfl_sync(0xffffffffu, val, src);
            int   gi = __shfl_sync(0xffffffffu, vi,  src);
            unsigned m = __ballot_sync(0xffffffffu, v < ld);
            if (m) {
                int p = __ffs(m) - 1;
                float dn = __shfl_up_sync(0xffffffffu, ld, 1);
                int   in = __shfl_up_sync(0xffffffffu, li, 1);
                if (lane > p)       { ld = dn; li = in; }
                else if (lane == p) { ld = v;  li = gi; }
                thr = __shfl_sync(0xffffffffu, ld, 31);
            }
        }
    }

    float yv = y[li];
    #pragma unroll
    for (int o = 16; o; o >>= 1) yv += __shfl_xor_sync(0xffffffffu, yv, o);
    if (lane == 0) out[q] = yv * (1.0f / (float)KSEL);
}

// ---------------------------------------------------------------- launcher
extern "C" void kernel_launch(void* const* d_in, const int* in_sizes, int n_in,
                              void* d_out, int out_size) {
    const float* Qm = (const float*)d_in[0];
    const float* X  = (const float*)d_in[1];
    const float* y  = (const float*)d_in[2];
    const int q_total = in_sizes[0] / DDIM;   // 4096
    const int n       = in_sizes[2];          // 100000
    float* out = (float*)d_out;

    split_kernel<<<NPAD / 8, 256>>>(X, n);

    pad_kernel<<<1, 1>>>();
    pad_kernel<<<1, 1>>>();

    static int smem_set = 0;
    if (!smem_set) {
        cudaFuncSetAttribute(knn_main, cudaFuncAttributeMaxDynamicSharedMemorySize,
                             SM_TOTAL);
        smem_set = 1;
    }
    dim3 grid((q_total + QTILE - 1) / QTILE, SPLITS);
    knn_main<<<grid, NTHR, SM_TOTAL>>>(Qm, q_total);

    knn_refine<<<(q_total + 7) / 8, 256>>>(Qm, X, y, out, q_total, n);
}

// round 16
// speedup vs baseline: 2.1817x; 1.1126x over previous
#include <cuda_runtime.h>
#include <cuda_fp16.h>
#include <math_constants.h>
#include <cstdint>

// KNN screen-then-refine, round 16 = round-15 + single-ballot row scan:
// distributed threshold vector thrv (lane j = row j's KEEP-th best) +
// warp-reduced row mins -> ONE ballot per chunk for all 16 rows.
//  K2: 1-pass fp16 mma screen, QTILE=64 x CTILE=64, 256 thr, 2 CTAs/SM,
//      Q-frags in regs, triple-buffered X, 1 barrier/chunk, KEEP=16.
//  K3: exact fp32 refine of 8*16=128 survivors -> top-32 -> mean(y).
#define DDIM      128
#define QTILE     64
#define CTILE     64
#define SPLITS    4
#define NPAD      100352
#define PER_SPLIT (NPAD / SPLITS)      // 25088
#define CHUNKS    (PER_SPLIT / CTILE)  // 392
#define NSTRIP    8                    // 4 splits * 2 c-strips
#define KEEP      16                   // survivors kept per (query, strip)
#define KSEL      32                   // final exact top-k
#define QMAX      4096
#define NTHR      256
#define NBUF      3

#define QSTR      136                  // padded row stride in halfs
#define QS_OFF    0                    // 64*136*2 = 17408
#define XS_OFF    17408                // 3 bufs * 17408 = 52224
#define XBUF_SZ   17408
#define TSQ_OFF   69632                // 3 * 256 = 768
#define STAGE_OFF 70400                // 8 warps * 16*34*4 = 17408
#define SM_TOTAL  87808

__device__ __align__(16) __half g_xh[(size_t)NPAD * DDIM];
__device__ __align__(16) float  g_tsq[NPAD];
__device__ int g_idx[QMAX * NSTRIP * KEEP];

__device__ __forceinline__ uint32_t smem_u32(const void* p) {
    uint32_t a;
    asm("{ .reg .u64 t; cvta.to.shared.u64 t, %1; cvt.u32.u64 %0, t; }" : "=r"(a) : "l"(p));
    return a;
}
#define CPA16(dst, src) \
    asm volatile("cp.async.cg.shared.global [%0], [%1], 16;" :: "r"(dst), "l"(src))
#define CPA_COMMIT() asm volatile("cp.async.commit_group;" ::: "memory")

__device__ __forceinline__ void ldsm4(uint32_t* r, uint32_t a) {
    asm volatile("ldmatrix.sync.aligned.m8n8.x4.shared.b16 {%0,%1,%2,%3}, [%4];"
                 : "=r"(r[0]), "=r"(r[1]), "=r"(r[2]), "=r"(r[3]) : "r"(a));
}
__device__ __forceinline__ void mma16816(float* d, const uint32_t* a,
                                         uint32_t b0, uint32_t b1) {
    asm volatile("mma.sync.aligned.m16n8k16.row.col.f32.f16.f16.f32 "
                 "{%0,%1,%2,%3}, {%4,%5,%6,%7}, {%8,%9}, {%0,%1,%2,%3};"
                 : "+f"(d[0]), "+f"(d[1]), "+f"(d[2]), "+f"(d[3])
                 : "r"(a[0]), "r"(a[1]), "r"(a[2]), "r"(a[3]), "r"(b0), "r"(b1));
}
__device__ __forceinline__ uint32_t pkh(__half a, __half b) {
    __half2 t = __halves2half2(a, b);
    return *reinterpret_cast<uint32_t*>(&t);
}

__global__ void pad_kernel() {}    // keeps ncu -s window on knn_main

// ---------------------------------------------------------------- kernel 1
__global__ void split_kernel(const float* __restrict__ X, int n) {
    int row  = blockIdx.x * 8 + (threadIdx.x >> 5);
    int lane = threadIdx.x & 31;
    if (row >= NPAD) return;
    size_t base = (size_t)row * DDIM + lane * 4;
    if (row < n) {
        float4 v = reinterpret_cast<const float4*>(X + (size_t)row * DDIM)[lane];
        float ss = v.x * v.x + v.y * v.y + v.z * v.z + v.w * v.w;
        #pragma unroll
        for (int o = 16; o; o >>= 1) ss += __shfl_xor_sync(0xffffffffu, ss, o);
        if (lane == 0) g_tsq[row] = ss;
        *reinterpret_cast<uint2*>(g_xh + base) =
            make_uint2(pkh(__float2half_rn(v.x), __float2half_rn(v.y)),
                       pkh(__float2half_rn(v.z), __float2half_rn(v.w)));
    } else {
        if (lane == 0) g_tsq[row] = CUDART_INF_F;
        *reinterpret_cast<uint2*>(g_xh + base) = make_uint2(0u, 0u);
    }
}

// ---------------------------------------------------------------- loader
__device__ __forceinline__ void load_chunk(uint32_t sb, int cb, int buf, int tid) {
    #pragma unroll
    for (int t = 0; t < 4; t++) {
        int idx = t * NTHR + tid;
        int row = idx >> 4, c16 = idx & 15;
        const char* sp = reinterpret_cast<const char*>(
            g_xh + (size_t)(cb + row) * DDIM) + c16 * 16;
        CPA16(sb + XS_OFF + buf * XBUF_SZ + (uint32_t)(row * QSTR * 2 + c16 * 16), sp);
    }
    if (tid < 16) {
        const char* tp = reinterpret_cast<const char*>(g_tsq + cb) + tid * 16;
        CPA16(sb + TSQ_OFF + buf * 256 + tid * 16, tp);
    }
    CPA_COMMIT();
}

// ---------------------------------------------------------------- kernel 2
__global__ void __launch_bounds__(NTHR, 2)
knn_main(const float* __restrict__ Qm, int q_total) {
    extern __shared__ char smem[];
    uint32_t sb = smem_u32(smem);
    const int tid  = threadIdx.x;
    const int lane = tid & 31;
    const int warp = tid >> 5;
    const int wm   = warp >> 1;          // 0..3 : q strip of 16
    const int wn   = warp & 1;           // 0..1 : c strip of 32
    const int split = blockIdx.y;
    const int qbase = blockIdx.x * QTILE;
    const int sbase = split * PER_SPLIT;

    load_chunk(sb, sbase, 0, tid);                 // chunk 0
    if (1 < CHUNKS) load_chunk(sb, sbase + CTILE, 1, tid);   // chunk 1

    // Q (-2x, fp16) -> smem
    __half* qs = reinterpret_cast<__half*>(smem + QS_OFF);
    for (int i = tid; i < QTILE * DDIM; i += NTHR) {
        int row = i >> 7, k = i & 127;
        int q = qbase + row; if (q >= q_total) q = q_total - 1;
        qs[row * QSTR + k] = __float2half_rn(-2.f * Qm[(size_t)q * DDIM + k]);
    }
    __syncthreads();

    // Hoist Q a-fragments into registers once.
    const uint32_t a_off = sb + QS_OFF
        + (uint32_t)((wm * 16 + (lane & 15)) * QSTR + (lane >> 4) * 8) * 2;
    uint32_t af[8][4];
    #pragma unroll
    for (int ks = 0; ks < 8; ks++) ldsm4(af[ks], a_off + ks * 32);

    float ld[16]; int li[16];
    #pragma unroll
    for (int j = 0; j < 16; j++) { ld[j] = CUDART_INF_F; li[j] = 0; }
    float thrv = CUDART_INF_F;          // lane j: row j's KEEP-th best (j<16)

    const int r0 = lane >> 2;
    const uint32_t b_off0 = (uint32_t)((wn * 32 + (lane & 15)) * QSTR + (lane >> 4) * 8) * 2;
    const uint32_t b_off1 = b_off0 + (uint32_t)(16 * QSTR * 2);
    float* stg = reinterpret_cast<float*>(smem + STAGE_OFF) + warp * (16 * 34);
    const int gsrc = (lane & 7) * 4;    // gather source lane for row mins

    for (int i = 0; i < CHUNKS; i++) {
        const int cur = i % NBUF;
        if (i + 1 < CHUNKS) {
            asm volatile("cp.async.wait_group 1;" ::: "memory");
        } else {
            asm volatile("cp.async.wait_group 0;" ::: "memory");
        }
        __syncthreads();
        if (i + 2 < CHUNKS)
            load_chunk(sb, sbase + (i + 2) * CTILE, (i + 2) % NBUF, tid);

        float acc[4][4];
        #pragma unroll
        for (int nt = 0; nt < 4; nt++)
            #pragma unroll
            for (int e = 0; e < 4; e++) acc[nt][e] = 0.f;

        const uint32_t xb = sb + XS_OFF + cur * XBUF_SZ;
        #pragma unroll
        for (int ks = 0; ks < 8; ks++) {
            uint32_t b0v[4], b1v[4];
            ldsm4(b0v, xb + b_off0 + ks * 32);
            ldsm4(b1v, xb + b_off1 + ks * 32);
            mma16816(acc[0], af[ks], b0v[0], b0v[2]);
            mma16816(acc[1], af[ks], b0v[1], b0v[3]);
            mma16816(acc[2], af[ks], b1v[0], b1v[2]);
            mma16816(acc[3], af[ks], b1v[1], b1v[3]);
        }

        // fold tsq into accumulators (scores complete in registers)
        const float* tsq_s = reinterpret_cast<const float*>(smem + TSQ_OFF + cur * 256);
        #pragma unroll
        for (int nt = 0; nt < 4; nt++) {
            float2 t2 = *reinterpret_cast<const float2*>(
                &tsq_s[wn * 32 + nt * 8 + (lane & 3) * 2]);
            acc[nt][0] += t2.x;  acc[nt][1] += t2.y;
            acc[nt][2] += t2.x;  acc[nt][3] += t2.y;
        }

        // per-lane mins (rows r0 / r0+8), then warp-reduce over 4 owner lanes
        float minA = fminf(fminf(fminf(acc[0][0], acc[0][1]), fminf(acc[1][0], acc[1][1])),
                           fminf(fminf(acc[2][0], acc[2][1]), fminf(acc[3][0], acc[3][1])));
        float minB = fminf(fminf(fminf(acc[0][2], acc[0][3]), fminf(acc[1][2], acc[1][3])),
                           fminf(fminf(acc[2][2], acc[2][3]), fminf(acc[3][2], acc[3][3])));
        minA = fminf(minA, __shfl_xor_sync(0xffffffffu, minA, 1));
        minA = fminf(minA, __shfl_xor_sync(0xffffffffu, minA, 2));
        minB = fminf(minB, __shfl_xor_sync(0xffffffffu, minB, 1));
        minB = fminf(minB, __shfl_xor_sync(0xffffffffu, minB, 2));
        // gather: lane j<8 takes row-j min (from lane 4j); lane j in 8..15 row j
        float gA = __shfl_sync(0xffffffffu, minA, gsrc);
        float gB = __shfl_sync(0xffffffffu, minB, gsrc);
        float rowmin = (lane < 8) ? gA : gB;
        unsigned hitm = __ballot_sync(0xffffffffu, rowmin < thrv) & 0xFFFFu;

        if (hitm) {
            const int cbase = sbase + i * CTILE + wn * 32;
            #pragma unroll
            for (int j = 0; j < 16; j++) {
                if ((hitm >> j) & 1u) {
                    const int e0 = (j < 8) ? 0 : 2;
                    if (r0 == (j & 7)) {
                        #pragma unroll
                        for (int nt = 0; nt < 4; nt++)
                            *reinterpret_cast<float2*>(
                                &stg[j * 34 + nt * 8 + (lane & 3) * 2]) =
                                make_float2(acc[nt][e0], acc[nt][e0 + 1]);
                    }
                    __syncwarp();
                    float val = stg[j * 34 + lane];
                    float thr = __shfl_sync(0xffffffffu, thrv, j);
                    unsigned pass = __ballot_sync(0xffffffffu, val < thr);
                    while (pass) {
                        int src = __ffs(pass) - 1;
                        pass &= pass - 1;
                        float v  = __shfl_sync(0xffffffffu, val, src);
                        int   gi = cbase + src;
                        unsigned m = __ballot_sync(0xffffffffu, v < ld[j]);
                        if (m) {
                            int p = __ffs(m) - 1;
                            float dn = __shfl_up_sync(0xffffffffu, ld[j], 1);
                            int   in = __shfl_up_sync(0xffffffffu, li[j], 1);
                            if (lane > p)       { ld[j] = dn; li[j] = in; }
                            else if (lane == p) { ld[j] = v;  li[j] = gi; }
                            thr = __shfl_sync(0xffffffffu, ld[j], KEEP - 1);
                            pass &= __ballot_sync(0xffffffffu, val < thr);
                        }
                    }
                    if (lane == j) thrv = thr;   // refresh distributed threshold
                }
            }
        }
    }

    // emit top-KEEP per (query, strip): lanes 0..KEEP-1
    const int strip = split * 2 + wn;
    if (lane < KEEP) {
        #pragma unroll
        for (int j = 0; j < 16; j++) {
            int q = qbase + wm * 16 + j;
            if (q < q_total)
                g_idx[(q * NSTRIP + strip) * KEEP + lane] = li[j];
        }
    }
}

// ---------------------------------------------------------------- kernel 3
// 128 survivors per query -> exact fp32 top-32 -> mean(y).
__global__ void __launch_bounds__(256, 4)
knn_refine(const float* __restrict__ Qm, const float* __restrict__ X,
           const float* __restrict__ y, float* __restrict__ out,
           int q_total, int n) {
    __shared__ __align__(16) float qsm[8][DDIM];
    const int lane = threadIdx.x & 31;
    const int warp = threadIdx.x >> 5;
    const int q = blockIdx.x * 8 + warp;
    if (q >= q_total) return;

    reinterpret_cast<float4*>(qsm[warp])[lane] =
        reinterpret_cast<const float4*>(Qm + (size_t)q * DDIM)[lane];
    __syncwarp();
    const float4* q4 = reinterpret_cast<const float4*>(qsm[warp]);

    float ld = CUDART_INF_F;
    int   li = 0;
    const int* ip = g_idx + (size_t)q * NSTRIP * KEEP;   // 128 ints

    #pragma unroll 1
    for (int g = 0; g < (NSTRIP * KEEP) / 32; g++) {     // 4 rounds
        int idx = ip[g * 32 + lane];
        if (idx >= n) idx = n - 1;
        const float4* xr = reinterpret_cast<const float4*>(X + (size_t)idx * DDIM);
        float a0 = 0.f, a1 = 0.f, a2 = 0.f, a3 = 0.f;
        #pragma unroll 8
        for (int kk = 0; kk < 32; kk++) {
            float4 xv = xr[kk];
            float4 qv = q4[kk];
            a0 = fmaf(qv.x, xv.x, a0);
            a1 = fmaf(qv.y, xv.y, a1);
            a2 = fmaf(qv.z, xv.z, a2);
            a3 = fmaf(qv.w, xv.w, a3);
        }
        float val = fmaf(-2.f, (a0 + a1) + (a2 + a3), g_tsq[idx]);
        int   vi  = idx;
        float thr = __shfl_sync(0xffffffffu, ld, 31);
        unsigned pass = __ballot_sync(0xffffffffu, val < thr);
        while (pass) {
            int src = __ffs(pass) - 1;
            pass &= pass - 1;
            float v  = __shfl_sync(0xffffffffu, val, src);
            int   gi = __shfl_sync(0xffffffffu, vi,  src);
            unsigned m = __ballot_sync(0xffffffffu, v < ld);
            if (m) {
                int p = __ffs(m) - 1;
                float dn = __shfl_up_sync(0xffffffffu, ld, 1);
                int   in = __shfl_up_sync(0xffffffffu, li, 1);
                if (lane > p)       { ld = dn; li = in; }
                else if (lane == p) { ld = v;  li = gi; }
                thr = __shfl_sync(0xffffffffu, ld, 31);
            }
        }
    }

    float yv = y[li];
    #pragma unroll
    for (int o = 16; o; o >>= 1) yv += __shfl_xor_sync(0xffffffffu, yv, o);
    if (lane == 0) out[q] = yv * (1.0f / (float)KSEL);
}

// ---------------------------------------------------------------- launcher
extern "C" void kernel_launch(void* const* d_in, const int* in_sizes, int n_in,
                              void* d_out, int out_size) {
    const float* Qm = (const float*)d_in[0];
    const float* X  = (const float*)d_in[1];
    const float* y  = (const float*)d_in[2];
    const int q_total = in_sizes[0] / DDIM;   // 4096
    const int n       = in_sizes[2];          // 100000
    float* out = (float*)d_out;

    split_kernel<<<NPAD / 8, 256>>>(X, n);

    pad_kernel<<<1, 1>>>();
    pad_kernel<<<1, 1>>>();

    static int smem_set = 0;
    if (!smem_set) {
        cudaFuncSetAttribute(knn_main, cudaFuncAttributeMaxDynamicSharedMemorySize,
                             SM_TOTAL);
        smem_set = 1;
    }
    dim3 grid((q_total + QTILE - 1) / QTILE, SPLITS);
    knn_main<<<grid, NTHR, SM_TOTAL>>>(Qm, q_total);

    knn_refine<<<(q_total + 7) / 8, 256>>>(Qm, X, y, out, q_total, n);
}

// round 17
// speedup vs baseline: 2.3642x; 1.0836x over previous
#include <cuda_runtime.h>
#include <cuda_fp16.h>
#include <math_constants.h>
#include <cstdint>

// KNN screen-then-refine, round 17 = round-16 + CTILE=128 (two 64c sub-tiles
// per barrier): halves barrier/wait_group/loader fixed costs. NBUF=2.
//  K2: 1-pass fp16 mma screen, QTILE=64, 256 thr, 2 CTAs/SM, Q-frags in regs,
//      single-ballot row scan, KEEP=16.
//  K3: exact fp32 refine of 8*16=128 survivors -> top-32 -> mean(y).
#define DDIM      128
#define QTILE     64
#define CTILE     128
#define SPLITS    4
#define NPAD      100352
#define PER_SPLIT (NPAD / SPLITS)      // 25088
#define CHUNKS    (PER_SPLIT / CTILE)  // 196
#define NSTRIP    8                    // 4 splits * 2 c-strips
#define KEEP      16
#define KSEL      32
#define QMAX      4096
#define NTHR      256
#define NBUF      2

#define QSTR      136                  // padded row stride in halfs
#define QS_OFF    0                    // 64*136*2 = 17408
#define XS_OFF    17408                // 2 bufs * 128*272 = 69632
#define XBUF_SZ   34816
#define TSQ_OFF   87040                // 2 * 512 = 1024
#define STAGE_OFF 88064                // 8 warps * 16*34*4 = 17408
#define SM_TOTAL  105472

__device__ __align__(16) __half g_xh[(size_t)NPAD * DDIM];
__device__ __align__(16) float  g_tsq[NPAD];
__device__ int g_idx[QMAX * NSTRIP * KEEP];

__device__ __forceinline__ uint32_t smem_u32(const void* p) {
    uint32_t a;
    asm("{ .reg .u64 t; cvta.to.shared.u64 t, %1; cvt.u32.u64 %0, t; }" : "=r"(a) : "l"(p));
    return a;
}
#define CPA16(dst, src) \
    asm volatile("cp.async.cg.shared.global [%0], [%1], 16;" :: "r"(dst), "l"(src))
#define CPA_COMMIT() asm volatile("cp.async.commit_group;" ::: "memory")

__device__ __forceinline__ void ldsm4(uint32_t* r, uint32_t a) {
    asm volatile("ldmatrix.sync.aligned.m8n8.x4.shared.b16 {%0,%1,%2,%3}, [%4];"
                 : "=r"(r[0]), "=r"(r[1]), "=r"(r[2]), "=r"(r[3]) : "r"(a));
}
__device__ __forceinline__ void mma16816(float* d, const uint32_t* a,
                                         uint32_t b0, uint32_t b1) {
    asm volatile("mma.sync.aligned.m16n8k16.row.col.f32.f16.f16.f32 "
                 "{%0,%1,%2,%3}, {%4,%5,%6,%7}, {%8,%9}, {%0,%1,%2,%3};"
                 : "+f"(d[0]), "+f"(d[1]), "+f"(d[2]), "+f"(d[3])
                 : "r"(a[0]), "r"(a[1]), "r"(a[2]), "r"(a[3]), "r"(b0), "r"(b1));
}
__device__ __forceinline__ uint32_t pkh(__half a, __half b) {
    __half2 t = __halves2half2(a, b);
    return *reinterpret_cast<uint32_t*>(&t);
}

__global__ void pad_kernel() {}    // keeps ncu -s window on knn_main

// ---------------------------------------------------------------- kernel 1
__global__ void split_kernel(const float* __restrict__ X, int n) {
    int row  = blockIdx.x * 8 + (threadIdx.x >> 5);
    int lane = threadIdx.x & 31;
    if (row >= NPAD) return;
    size_t base = (size_t)row * DDIM + lane * 4;
    if (row < n) {
        float4 v = reinterpret_cast<const float4*>(X + (size_t)row * DDIM)[lane];
        float ss = v.x * v.x + v.y * v.y + v.z * v.z + v.w * v.w;
        #pragma unroll
        for (int o = 16; o; o >>= 1) ss += __shfl_xor_sync(0xffffffffu, ss, o);
        if (lane == 0) g_tsq[row] = ss;
        *reinterpret_cast<uint2*>(g_xh + base) =
            make_uint2(pkh(__float2half_rn(v.x), __float2half_rn(v.y)),
                       pkh(__float2half_rn(v.z), __float2half_rn(v.w)));
    } else {
        if (lane == 0) g_tsq[row] = CUDART_INF_F;
        *reinterpret_cast<uint2*>(g_xh + base) = make_uint2(0u, 0u);
    }
}

// ---------------------------------------------------------------- loader
// 128 rows * 256B = 2048 x 16B transfers -> 8 per thread; + tsq 512B.
__device__ __forceinline__ void load_chunk(uint32_t sb, int cb, int buf, int tid) {
    #pragma unroll
    for (int t = 0; t < 8; t++) {
        int idx = t * NTHR + tid;
        int row = idx >> 4, c16 = idx & 15;
        const char* sp = reinterpret_cast<const char*>(
            g_xh + (size_t)(cb + row) * DDIM) + c16 * 16;
        CPA16(sb + XS_OFF + buf * XBUF_SZ + (uint32_t)(row * QSTR * 2 + c16 * 16), sp);
    }
    if (tid < 32) {
        const char* tp = reinterpret_cast<const char*>(g_tsq + cb) + tid * 16;
        CPA16(sb + TSQ_OFF + buf * 512 + tid * 16, tp);
    }
    CPA_COMMIT();
}

// ---------------------------------------------------------------- kernel 2
__global__ void __launch_bounds__(NTHR, 2)
knn_main(const float* __restrict__ Qm, int q_total) {
    extern __shared__ char smem[];
    uint32_t sb = smem_u32(smem);
    const int tid  = threadIdx.x;
    const int lane = tid & 31;
    const int warp = tid >> 5;
    const int wm   = warp >> 1;          // 0..3 : q strip of 16
    const int wn   = warp & 1;           // 0..1 : c strip of 32
    const int split = blockIdx.y;
    const int qbase = blockIdx.x * QTILE;
    const int sbase = split * PER_SPLIT;

    load_chunk(sb, sbase, 0, tid);       // chunk 0 in flight

    // Q (-2x, fp16) -> smem
    __half* qs = reinterpret_cast<__half*>(smem + QS_OFF);
    for (int i = tid; i < QTILE * DDIM; i += NTHR) {
        int row = i >> 7, k = i & 127;
        int q = qbase + row; if (q >= q_total) q = q_total - 1;
        qs[row * QSTR + k] = __float2half_rn(-2.f * Qm[(size_t)q * DDIM + k]);
    }
    __syncthreads();

    // Hoist Q a-fragments into registers once.
    const uint32_t a_off = sb + QS_OFF
        + (uint32_t)((wm * 16 + (lane & 15)) * QSTR + (lane >> 4) * 8) * 2;
    uint32_t af[8][4];
    #pragma unroll
    for (int ks = 0; ks < 8; ks++) ldsm4(af[ks], a_off + ks * 32);

    float ld[16]; int li[16];
    #pragma unroll
    for (int j = 0; j < 16; j++) { ld[j] = CUDART_INF_F; li[j] = 0; }
    float thrv = CUDART_INF_F;          // lane j: row j's KEEP-th best (j<16)

    const int r0 = lane >> 2;
    const uint32_t b_base = (uint32_t)((wn * 32 + (lane & 15)) * QSTR + (lane >> 4) * 8) * 2;
    float* stg = reinterpret_cast<float*>(smem + STAGE_OFF) + warp * (16 * 34);
    const int gsrc = (lane & 7) * 4;

    for (int i = 0; i < CHUNKS; i++) {
        const int cur = i & 1;
        asm volatile("cp.async.wait_group 0;" ::: "memory");
        __syncthreads();                 // chunk i visible; buf cur^1 free
        if (i + 1 < CHUNKS)
            load_chunk(sb, sbase + (i + 1) * CTILE, cur ^ 1, tid);

        const uint32_t xb = sb + XS_OFF + cur * XBUF_SZ;
        const float* tsq_s = reinterpret_cast<const float*>(smem + TSQ_OFF + cur * 512);

        #pragma unroll
        for (int sub = 0; sub < 2; sub++) {
            const uint32_t b_off0 = xb + b_base + (uint32_t)(sub * 64 * QSTR * 2);
            const uint32_t b_off1 = b_off0 + (uint32_t)(16 * QSTR * 2);

            float acc[4][4];
            #pragma unroll
            for (int nt = 0; nt < 4; nt++)
                #pragma unroll
                for (int e = 0; e < 4; e++) acc[nt][e] = 0.f;

            #pragma unroll
            for (int ks = 0; ks < 8; ks++) {
                uint32_t b0v[4], b1v[4];
                ldsm4(b0v, b_off0 + ks * 32);
                ldsm4(b1v, b_off1 + ks * 32);
                mma16816(acc[0], af[ks], b0v[0], b0v[2]);
                mma16816(acc[1], af[ks], b0v[1], b0v[3]);
                mma16816(acc[2], af[ks], b1v[0], b1v[2]);
                mma16816(acc[3], af[ks], b1v[1], b1v[3]);
            }

            // fold tsq (scores complete in registers)
            const float* ts = tsq_s + sub * 64;
            #pragma unroll
            for (int nt = 0; nt < 4; nt++) {
                float2 t2 = *reinterpret_cast<const float2*>(
                    &ts[wn * 32 + nt * 8 + (lane & 3) * 2]);
                acc[nt][0] += t2.x;  acc[nt][1] += t2.y;
                acc[nt][2] += t2.x;  acc[nt][3] += t2.y;
            }

            // per-lane mins, warp-reduce over 4 owner lanes, gather, 1 ballot
            float minA = fminf(fminf(fminf(acc[0][0], acc[0][1]), fminf(acc[1][0], acc[1][1])),
                               fminf(fminf(acc[2][0], acc[2][1]), fminf(acc[3][0], acc[3][1])));
            float minB = fminf(fminf(fminf(acc[0][2], acc[0][3]), fminf(acc[1][2], acc[1][3])),
                               fminf(fminf(acc[2][2], acc[2][3]), fminf(acc[3][2], acc[3][3])));
            minA = fminf(minA, __shfl_xor_sync(0xffffffffu, minA, 1));
            minA = fminf(minA, __shfl_xor_sync(0xffffffffu, minA, 2));
            minB = fminf(minB, __shfl_xor_sync(0xffffffffu, minB, 1));
            minB = fminf(minB, __shfl_xor_sync(0xffffffffu, minB, 2));
            float gA = __shfl_sync(0xffffffffu, minA, gsrc);
            float gB = __shfl_sync(0xffffffffu, minB, gsrc);
            float rowmin = (lane < 8) ? gA : gB;
            unsigned hitm = __ballot_sync(0xffffffffu, rowmin < thrv) & 0xFFFFu;

            if (hitm) {
                const int cbase = sbase + i * CTILE + sub * 64 + wn * 32;
                #pragma unroll
                for (int j = 0; j < 16; j++) {
                    if ((hitm >> j) & 1u) {
                        const int e0 = (j < 8) ? 0 : 2;
                        if (r0 == (j & 7)) {
                            #pragma unroll
                            for (int nt = 0; nt < 4; nt++)
                                *reinterpret_cast<float2*>(
                                    &stg[j * 34 + nt * 8 + (lane & 3) * 2]) =
                                    make_float2(acc[nt][e0], acc[nt][e0 + 1]);
                        }
                        __syncwarp();
                        float val = stg[j * 34 + lane];
                        float thr = __shfl_sync(0xffffffffu, thrv, j);
                        unsigned pass = __ballot_sync(0xffffffffu, val < thr);
                        while (pass) {
                            int src = __ffs(pass) - 1;
                            pass &= pass - 1;
                            float v  = __shfl_sync(0xffffffffu, val, src);
                            int   gi = cbase + src;
                            unsigned m = __ballot_sync(0xffffffffu, v < ld[j]);
                            if (m) {
                                int p = __ffs(m) - 1;
                                float dn = __shfl_up_sync(0xffffffffu, ld[j], 1);
                                int   in = __shfl_up_sync(0xffffffffu, li[j], 1);
                                if (lane > p)       { ld[j] = dn; li[j] = in; }
                                else if (lane == p) { ld[j] = v;  li[j] = gi; }
                                thr = __shfl_sync(0xffffffffu, ld[j], KEEP - 1);
                                pass &= __ballot_sync(0xffffffffu, val < thr);
                            }
                        }
                        if (lane == j) thrv = thr;
                    }
                }
            }
        }
    }

    // emit top-KEEP per (query, strip): lanes 0..KEEP-1
    const int strip = split * 2 + wn;
    if (lane < KEEP) {
        #pragma unroll
        for (int j = 0; j < 16; j++) {
            int q = qbase + wm * 16 + j;
            if (q < q_total)
                g_idx[(q * NSTRIP + strip) * KEEP + lane] = li[j];
        }
    }
}

// ---------------------------------------------------------------- kernel 3
// 128 survivors per query -> exact fp32 top-32 -> mean(y).
__global__ void __launch_bounds__(256, 4)
knn_refine(const float* __restrict__ Qm, const float* __restrict__ X,
           const float* __restrict__ y, float* __restrict__ out,
           int q_total, int n) {
    __shared__ __align__(16) float qsm[8][DDIM];
    const int lane = threadIdx.x & 31;
    const int warp = threadIdx.x >> 5;
    const int q = blockIdx.x * 8 + warp;
    if (q >= q_total) return;

    reinterpret_cast<float4*>(qsm[warp])[lane] =
        reinterpret_cast<const float4*>(Qm + (size_t)q * DDIM)[lane];
    __syncwarp();
    const float4* q4 = reinterpret_cast<const float4*>(qsm[warp]);

    float ld = CUDART_INF_F;
    int   li = 0;
    const int* ip = g_idx + (size_t)q * NSTRIP * KEEP;   // 128 ints

    #pragma unroll 1
    for (int g = 0; g < (NSTRIP * KEEP) / 32; g++) {     // 4 rounds
        int idx = ip[g * 32 + lane];
        if (idx >= n) idx = n - 1;
        const float4* xr = reinterpret_cast<const float4*>(X + (size_t)idx * DDIM);
        float a0 = 0.f, a1 = 0.f, a2 = 0.f, a3 = 0.f;
        #pragma unroll 8
        for (int kk = 0; kk < 32; kk++) {
            float4 xv = xr[kk];
            float4 qv = q4[kk];
            a0 = fmaf(qv.x, xv.x, a0);
            a1 = fmaf(qv.y, xv.y, a1);
            a2 = fmaf(qv.z, xv.z, a2);
            a3 = fmaf(qv.w, xv.w, a3);
        }
        float val = fmaf(-2.f, (a0 + a1) + (a2 + a3), g_tsq[idx]);
        int   vi  = idx;
        float thr = __shfl_sync(0xffffffffu, ld, 31);
        unsigned pass = __ballot_sync(0xffffffffu, val < thr);
        while (pass) {
            int src = __ffs(pass) - 1;
            pass &= pass - 1;
            float v  = __shfl_sync(0xffffffffu, val, src);
            int   gi = __shfl_sync(0xffffffffu, vi,  src);
            unsigned m = __ballot_sync(0xffffffffu, v < ld);
            if (m) {
                int p = __ffs(m) - 1;
                float dn = __shfl_up_sync(0xffffffffu, ld, 1);
                int   in = __shfl_up_sync(0xffffffffu, li, 1);
                if (lane > p)       { ld = dn; li = in; }
                else if (lane == p) { ld = v;  li = gi; }
                thr = __shfl_sync(0xffffffffu, ld, 31);
            }
        }
    }

    float yv = y[li];
    #pragma unroll
    for (int o = 16; o; o >>= 1) yv += __shfl_xor_sync(0xffffffffu, yv, o);
    if (lane == 0) out[q] = yv * (1.0f / (float)KSEL);
}

// ---------------------------------------------------------------- launcher
extern "C" void kernel_launch(void* const* d_in, const int* in_sizes, int n_in,
                              void* d_out, int out_size) {
    const float* Qm = (const float*)d_in[0];
    const float* X  = (const float*)d_in[1];
    const float* y  = (const float*)d_in[2];
    const int q_total = in_sizes[0] / DDIM;   // 4096
    const int n       = in_sizes[2];          // 100000
    float* out = (float*)d_out;

    split_kernel<<<NPAD / 8, 256>>>(X, n);

    pad_kernel<<<1, 1>>>();
    pad_kernel<<<1, 1>>>();

    static int smem_set = 0;
    if (!smem_set) {
        cudaFuncSetAttribute(knn_main, cudaFuncAttributeMaxDynamicSharedMemorySize,
                             SM_TOTAL);
        smem_set = 1;
    }
    dim3 grid((q_total + QTILE - 1) / QTILE, SPLITS);
    knn_main<<<grid, NTHR, SM_TOTAL>>>(Qm, q_total);

    knn_refine<<<(q_total + 7) / 8, 256>>>(Qm, X, y, out, q_total, n);
}